// round 9
// baseline (speedup 1.0000x reference)
#include <cuda_runtime.h>
#include <cuda_fp16.h>
#include <math.h>

#define B_  512
#define R_  1152
#define C_  8
#define J_  10
#define O_  16
#define JO_ 160

// Scratch (device globals: no allocations allowed in kernel_launch)
// u_hat stored fp16, packed across batch pairs: g_U16[p, r, jo] = (u[2p], u[2p+1])
__device__ __half2 g_U16[(size_t)(B_ / 2) * R_ * JO_];   // 188 MB
__device__ float   g_S[3][B_ * JO_];                     // s accumulators
__device__ float   g_V0[B_ * JO_];                       // v0
__device__ float   g_VSUM[B_ * JO_];                     // v0 + v1

__device__ __forceinline__ __half2 h2exp2_(__half2 x) {
    unsigned r, xi = *reinterpret_cast<unsigned*>(&x);
    asm("ex2.approx.f16x2 %0, %1;" : "=r"(r) : "r"(xi));
    return *reinterpret_cast<__half2*>(&r);
}

// ---------------------------------------------------------------------------
__global__ void k_zero() {
    int i = blockIdx.x * blockDim.x + threadIdx.x;
    if (i < 3 * B_ * JO_) ((float*)g_S)[i] = 0.0f;
}

// ---------------------------------------------------------------------------
// u_hat[b,r,jo] = sum_c W[r,jo,c] * x[b,r,c]; fused sum_r u_hat -> g_S[0].
// Each warp owns (8 batches = 4 pairs, 4-r slice). W[r] in 40 regs, reused
// across 8 batches; compute fp32, store packed half2.
// v4: sacc packed half2 over b-pairs (-20 regs) + __launch_bounds__(256,3)
// -> 24 warps/SM (was 16); 4-r units / 2304 blocks to smooth wave tail.
__global__ void __launch_bounds__(256, 3) k_uhat(const float* __restrict__ x,
                                                 const float* __restrict__ W) {
    const int tid  = threadIdx.x;
    const int lane = tid & 31;
    const int unit = blockIdx.x * 8 + (tid >> 5);
    const int bg   = unit / 288;           // 64 groups of 8 b
    const int sl   = unit - bg * 288;      // 288 slices of 4 r
    const int b0   = bg * 8;
    const int r0   = sl * 4;

    __half2 sacc2[4][5];                   // per b-pair, per k
    #pragma unroll
    for (int pp = 0; pp < 4; pp++)
        #pragma unroll
        for (int k = 0; k < 5; k++) sacc2[pp][k] = __half2half2(__float2half(0.f));

    // x chunk: per b, 4 r x 8 c = 32 floats, one coalesced load each
    float xq[8];
    #pragma unroll
    for (int bb = 0; bb < 8; bb++)
        xq[bb] = x[(size_t)(b0 + bb) * (R_ * C_) + (size_t)r0 * C_ + lane];

    #pragma unroll
    for (int rr = 0; rr < 4; rr++) {
        const int r = r0 + rr;

        // W[r] -> registers: lane l holds W[r, l+32k, 0..8) as 2 float4
        float4 wa[5], wb[5];
        const float4* Wp =
            (const float4*)(W + (size_t)r * 1280 + (size_t)lane * 8);
        #pragma unroll
        for (int k = 0; k < 5; k++) {
            wa[k] = Wp[k * 64];
            wb[k] = Wp[k * 64 + 1];
        }

        float uhold[5];
        #pragma unroll
        for (int bb = 0; bb < 8; bb++) {
            float xc[8];
            #pragma unroll
            for (int c = 0; c < 8; c++)
                xc[c] = __shfl_sync(0xffffffffu, xq[bb], rr * 8 + c);

            float u[5];
            #pragma unroll
            for (int k = 0; k < 5; k++) {
                float t = wa[k].x * xc[0];
                t = fmaf(wa[k].y, xc[1], t);
                t = fmaf(wa[k].z, xc[2], t);
                t = fmaf(wa[k].w, xc[3], t);
                t = fmaf(wb[k].x, xc[4], t);
                t = fmaf(wb[k].y, xc[5], t);
                t = fmaf(wb[k].z, xc[6], t);
                t = fmaf(wb[k].w, xc[7], t);
                u[k] = t;
            }

            if (bb & 1) {
                const int pp = bb >> 1;
                __half2* up = g_U16 +
                    ((size_t)((b0 >> 1) + pp) * R_ + r) * JO_ + lane;
                #pragma unroll
                for (int k = 0; k < 5; k++) {
                    __half2 h = __floats2half2_rn(uhold[k], u[k]);
                    up[32 * k] = h;
                    sacc2[pp][k] = __hadd2(sacc2[pp][k], h);
                }
            } else {
                #pragma unroll
                for (int k = 0; k < 5; k++) uhold[k] = u[k];
            }
        }
    }

    #pragma unroll
    for (int pp = 0; pp < 4; pp++)
        #pragma unroll
        for (int k = 0; k < 5; k++) {
            float2 s = __half22float2(sacc2[pp][k]);
            int jo = lane + 32 * k;
            atomicAdd(&g_S[0][(b0 + 2 * pp)     * JO_ + jo], s.x);
            atomicAdd(&g_S[0][(b0 + 2 * pp + 1) * JO_ + jo], s.y);
        }
}

// ---------------------------------------------------------------------------
// One routing iteration on a BATCH PAIR per warp: logits for b0 and b1 ride
// in the .x/.y halves of every half2 through the butterfly AND the softmax
// tail: max-subtract (HMAX2 tree), single ex2.approx.f16x2 per k, half2
// z-tree, h2rcp. Exponents <= 0 so fp16 exp cannot overflow; terms that
// underflow to 0 carry negligible routing weight. Accumulation fp32.
// Lane l holds jo = l + 32k: lanes 0-15 j=2k, lanes 16-31 j=2k+1.
// v4: 256 pairs x 64 slices of 18 r = 16384 units / 2048 blocks.
__global__ void __launch_bounds__(256, 7) k_route(int vsel, int ssel) {
    const int lane = threadIdx.x & 31;
    const int unit = blockIdx.x * 8 + (threadIdx.x >> 5);
    const int p    = unit >> 6;
    const int sl   = unit & 63;
    const int b0   = 2 * p, b1 = b0 + 1;

    const float* __restrict__ V = vsel ? g_VSUM : g_V0;
    const float LOG2E = 1.4426950408889634f;

    __half2 v2[5];
    float sacc0[5] = {0.f, 0.f, 0.f, 0.f, 0.f};
    float sacc1[5] = {0.f, 0.f, 0.f, 0.f, 0.f};
    #pragma unroll
    for (int k = 0; k < 5; k++) {
        int jo = lane + 32 * k;
        v2[k] = __floats2half2_rn(V[b0 * JO_ + jo] * LOG2E,
                                  V[b1 * JO_ + jo] * LOG2E);
    }

    const __half2* __restrict__ up =
        g_U16 + ((size_t)p * R_ + (size_t)sl * 18) * JO_ + lane;

    #pragma unroll 2
    for (int r = 0; r < 18; r++) {
        __half2 u2[5], ap2[5];
        #pragma unroll
        for (int k = 0; k < 5; k++) u2[k] = up[32 * k];
        up += JO_;

        #pragma unroll
        for (int k = 0; k < 5; k++) ap2[k] = __hmul2(u2[k], v2[k]);

        // reduce over o (16 lanes per j-group), both batches per op
        #pragma unroll
        for (int d = 1; d < 16; d <<= 1) {
            #pragma unroll
            for (int k = 0; k < 5; k++)
                ap2[k] = __hadd2(ap2[k],
                                 __shfl_xor_sync(0xffffffffu, ap2[k], d));
        }

        // max over all 10 j (both halves independently)
        __half2 m2 = __hmax2(ap2[0], ap2[1]);
        m2 = __hmax2(m2, ap2[2]);
        m2 = __hmax2(m2, ap2[3]);
        m2 = __hmax2(m2, ap2[4]);
        m2 = __hmax2(m2, __shfl_xor_sync(0xffffffffu, m2, 16));

        // e = exp2(a - m) in half2; z-tree in half2
        #pragma unroll
        for (int k = 0; k < 5; k++) ap2[k] = h2exp2_(__hsub2(ap2[k], m2));
        __half2 z2 = __hadd2(ap2[0], ap2[1]);
        z2 = __hadd2(z2, ap2[2]);
        z2 = __hadd2(z2, ap2[3]);
        z2 = __hadd2(z2, ap2[4]);
        z2 = __hadd2(z2, __shfl_xor_sync(0xffffffffu, z2, 16));
        __half2 rz2 = h2rcp(z2);

        #pragma unroll
        for (int k = 0; k < 5; k++) {
            float2 c  = __half22float2(__hmul2(ap2[k], rz2));
            float2 uf = __half22float2(u2[k]);
            sacc0[k] = fmaf(c.x, uf.x, sacc0[k]);
            sacc1[k] = fmaf(c.y, uf.y, sacc1[k]);
        }
    }

    float* __restrict__ Sout = g_S[ssel];
    #pragma unroll
    for (int k = 0; k < 5; k++) {
        atomicAdd(&Sout[b0 * JO_ + lane + 32 * k], sacc0[k]);
        atomicAdd(&Sout[b1 * JO_ + lane + 32 * k], sacc1[k]);
    }
}

// ---------------------------------------------------------------------------
// v = squash(S * scale). mode 0: write g_V0. mode 1: g_VSUM = v + g_V0.
// mode 2: write dout (final output, [B,J,O,1] contiguous).
__global__ void k_squash(int ssel, float scale, int mode,
                         float* __restrict__ dout) {
    int i = blockIdx.x * blockDim.x + threadIdx.x;   // over B*J = 5120
    if (i >= B_ * J_) return;
    const float* s = g_S[ssel] + (size_t)i * O_;

    float sv[O_];
    float sq = 0.f;
    #pragma unroll
    for (int o = 0; o < O_; o++) {
        float t = s[o] * scale;
        sv[o] = t;
        sq += t * t;
    }
    float f = (sq / (1.0f + sq)) * rsqrtf(sq + 1e-8f);

    #pragma unroll
    for (int o = 0; o < O_; o++) {
        float vv = sv[o] * f;
        if (mode == 0)      g_V0[(size_t)i * O_ + o]   = vv;
        else if (mode == 1) g_VSUM[(size_t)i * O_ + o] = vv + g_V0[(size_t)i * O_ + o];
        else                dout[(size_t)i * O_ + o]   = vv;
    }
}

// ---------------------------------------------------------------------------
extern "C" void kernel_launch(void* const* d_in, const int* in_sizes, int n_in,
                              void* d_out, int out_size) {
    const float* x = (const float*)d_in[0];   // [512,1152,8]
    const float* W = (const float*)d_in[1];   // [1152,10,16,8]
    float* out = (float*)d_out;               // [512,10,16,1]
    (void)in_sizes; (void)n_in; (void)out_size;

    k_zero<<<240, 1024>>>();                          // zero S0,S1,S2
    k_uhat<<<2304, 256>>>(x, W);                      // u_hat(fp16) + sum_r -> S0
    k_squash<<<20, 256>>>(0, 1.0f / (float)J_, 0, nullptr);  // v0
    k_route<<<2048, 256>>>(0, 1);                     // iter 1 -> S1 (logits u.v0)
    k_squash<<<20, 256>>>(1, 1.0f, 1, nullptr);       // v1, VSUM = v0+v1
    k_route<<<2048, 256>>>(1, 2);                     // iter 2 -> S2 (logits u.(v0+v1))
    k_squash<<<20, 256>>>(2, 1.0f, 2, out);           // v2 -> output
}